// round 6
// baseline (speedup 1.0000x reference)
#include <cuda_runtime.h>
#include <cstdint>
#include <cstring>
#include <vector>
#include <algorithm>

// ---------------------------------------------------------------------------
// CLOPLayer: out[b,c,i] = x[b,c,idx[i]], idx a fixed permutation from JAX
// threefry RNG (seed 42) + sequential neighbor-swap scan, recomputed bit-exact
// on the HOST every call. idx delivered by one ATS copy kernel (GB300 C2C).
// Gather kernel: one block per (plane, band); smem window stored in
// COMPONENT-PLANE layout — element j at sp[(j&3)*S + (j>>2)], S=Lc*56 — so
// the near-identity stride-4 gather reads consecutive smem words per lane
// (conflict-free) instead of the 4-way-conflicting naive layout. Host bakes
// the layout into the uint16 index table.
// ---------------------------------------------------------------------------

#define GH 224
#define GW 224
#define HW (GH * GW)          // 50176
#define HW4 (HW / 4)
#define W4 (GW / 4)           // 56
#define NPLANES 384           // 128 * 3
#define BAND 28
#define NBANDS (GH / BAND)    // 8
#define BANDW (BAND * GW)     // 6272
#define BANDW4 (BANDW / 4)    // 1568
#define HW16 (HW / 8)         // 6272 uint4 units of uint16 table

__device__ unsigned short g_idxl[HW];  // window-relative PHYS indices
__device__ int g_idx[HW];              // absolute indices (fallback path)

// ---- host(ATS) -> device idx copy kernel ----------------------------------
__global__ __launch_bounds__(256)
void write_idx_ats(const uint4* __restrict__ hsrc) {
    int i = blockIdx.x * blockDim.x + threadIdx.x;
    if (i < HW16) {
        reinterpret_cast<uint4*>(g_idxl)[i] = __ldg(&hsrc[i]);
    }
}

// ---- banded gather, compile-time window height Lc, component-plane smem ----
template <int Lc>
__global__ __launch_bounds__(256)
void clop_band_t(const float* __restrict__ x, float* __restrict__ out) {
    extern __shared__ float sp[];
    constexpr int S = Lc * W4;            // floats per component plane
    const int plane = blockIdx.x;
    const int band  = blockIdx.y;
    const float* src = x + (size_t)plane * HW;

    int ws = band * BAND - ((Lc - BAND) >> 1);   // toroidal window start row
    if (ws < 0) ws += GH;

    // fill: float4 m covers elements 4m..4m+3 -> sp[c*S + m], conflict-free STS
    constexpr int N4 = Lc * W4;
    {
        int row0 = threadIdx.x / W4;
        int c4   = threadIdx.x - row0 * W4;
        constexpr int ROWSTEP = 256 / W4;          // 4
        constexpr int REM = 256 - ROWSTEP * W4;    // 32
        int row = row0;
        int cc  = c4;
#pragma unroll
        for (int k = threadIdx.x; k < N4; k += 256) {
            int gr = ws + row;
            if (gr >= GH) gr -= GH;
            const int m = row * W4 + cc;
            float4 v = reinterpret_cast<const float4*>(src + (size_t)gr * GW)[cc];
            sp[m]         = v.x;
            sp[m + S]     = v.y;
            sp[m + 2 * S] = v.z;
            sp[m + 3 * S] = v.w;
            row += ROWSTEP;
            cc += REM;
            if (cc >= W4) { cc -= W4; row += 1; }
        }
    }
    __syncthreads();

    const size_t base = (size_t)band * BANDW;
    const ushort4* id4 = reinterpret_cast<const ushort4*>(g_idxl + base);
    float4* dst = reinterpret_cast<float4*>(out + (size_t)plane * HW + base);

#pragma unroll
    for (int k = threadIdx.x; k < BANDW4; k += 256) {
        ushort4 id = __ldg(&id4[k]);
        float4 v;
        v.x = sp[id.x];
        v.y = sp[id.y];
        v.z = sp[id.z];
        v.w = sp[id.w];
        __stcs(&dst[k], v);
    }
}

// ---- fallback: full-plane smem gather (proven, R1) --------------------------
__global__ __launch_bounds__(1024, 1)
void clop_gather(const float* __restrict__ x, float* __restrict__ out) {
    extern __shared__ float sp[];
    const size_t off = (size_t)blockIdx.x * HW;
    const float4* src = reinterpret_cast<const float4*>(x + off);
    float4* sp4 = reinterpret_cast<float4*>(sp);
    for (int k = threadIdx.x; k < HW4; k += 1024) sp4[k] = src[k];
    __syncthreads();
    float4* dst = reinterpret_cast<float4*>(out + off);
    const int4* idx4 = reinterpret_cast<const int4*>(g_idx);
    for (int k = threadIdx.x; k < HW4; k += 1024) {
        int4 id = __ldg(&idx4[k]);
        float4 v;
        v.x = sp[id.x]; v.y = sp[id.y]; v.z = sp[id.z]; v.w = sp[id.w];
        __stcs(&dst[k], v);
    }
}

// ---------------------------------------------------------------------------
// Host-side exact replication of the JAX RNG pipeline (partitionable threefry)
// ---------------------------------------------------------------------------

static inline uint32_t rotl32(uint32_t x, int d) {
    return (x << d) | (x >> (32 - d));
}

struct TFKey { uint32_t hi, lo; };

static void threefry2x32(uint32_t k0, uint32_t k1, uint32_t x0, uint32_t x1,
                         uint32_t* o0, uint32_t* o1) {
    const uint32_t ks0 = k0, ks1 = k1, ks2 = k0 ^ k1 ^ 0x1BD11BDAu;
    static const int ra[4] = {13, 15, 26, 6};
    static const int rb[4] = {17, 29, 16, 24};
    x0 += ks0; x1 += ks1;
    for (int i = 0; i < 4; i++) { x0 += x1; x1 = rotl32(x1, ra[i]); x1 ^= x0; }
    x0 += ks1; x1 += ks2 + 1u;
    for (int i = 0; i < 4; i++) { x0 += x1; x1 = rotl32(x1, rb[i]); x1 ^= x0; }
    x0 += ks2; x1 += ks0 + 2u;
    for (int i = 0; i < 4; i++) { x0 += x1; x1 = rotl32(x1, ra[i]); x1 ^= x0; }
    x0 += ks0; x1 += ks1 + 3u;
    for (int i = 0; i < 4; i++) { x0 += x1; x1 = rotl32(x1, rb[i]); x1 ^= x0; }
    x0 += ks1; x1 += ks2 + 4u;
    for (int i = 0; i < 4; i++) { x0 += x1; x1 = rotl32(x1, ra[i]); x1 ^= x0; }
    x0 += ks2; x1 += ks0 + 5u;
    *o0 = x0; *o1 = x1;
}

static inline TFKey tf_child(TFKey k, uint32_t j) {
    TFKey r; threefry2x32(k.hi, k.lo, 0u, j, &r.hi, &r.lo); return r;
}
static inline uint32_t tf_bits32(TFKey k, uint32_t i) {
    uint32_t a, b; threefry2x32(k.hi, k.lo, 0u, i, &a, &b); return a ^ b;
}

static void compute_host_idx(int* h_idx) {
    const int n = HW;
    TFKey key42 = {0u, 42u};
    TFKey k1 = tf_child(key42, 0u);
    TFKey k2 = tf_child(key42, 1u);

    std::vector<int> order(n);
    for (int i = 0; i < n; i++) order[i] = i;
    {
        TFKey cur = k1;
        std::vector<uint64_t> kv(n);
        std::vector<int> nx(n);
        for (int round = 0; round < 2; round++) {
            TFKey nkey = tf_child(cur, 0u);
            TFKey sub  = tf_child(cur, 1u);
            for (int i = 0; i < n; i++)
                kv[(size_t)i] = ((uint64_t)tf_bits32(sub, (uint32_t)i) << 32) |
                                (uint32_t)i;
            std::sort(kv.begin(), kv.end());
            for (int j = 0; j < n; j++)
                nx[(size_t)j] = order[(size_t)(uint32_t)kv[(size_t)j]];
            order.swap(nx);
            cur = nkey;
        }
    }

    float p0 = (float)(1.0 - 0.3), pq = (float)(0.3 / 4.0);
    float c[5];
    c[0] = p0;
    for (int j = 1; j < 5; j++) c[j] = c[j - 1] + pq;

    std::vector<uint8_t> rs(n);
    for (int i = 0; i < n; i++) {
        uint32_t bits = tf_bits32(k2, (uint32_t)i);
        uint32_t fb = (bits >> 9) | 0x3F800000u;
        float f; std::memcpy(&f, &fb, 4);
        f -= 1.0f;
        float r = c[4] * (1.0f - f);
        int ind = 0;
        while (ind < 5 && c[ind] < r) ind++;
        rs[(size_t)i] = (uint8_t)ind;
    }

    for (int i = 0; i < n; i++) h_idx[i] = i;
    for (int t = 0; t < n; t++) {
        const int a = order[(size_t)t];
        const int r = rs[(size_t)t];
        const int i = a / GW, j = a % GW;
        const int ii = (r == 1) ? (i + 1) % GH : (r == 2) ? (i + GH - 1) % GH : i;
        const int jj = (r == 3) ? (j + 1) % GW : (r == 4) ? (j + GW - 1) % GW : j;
        const int b = (r == 0) ? a : (ii * GW + jj);
        const int va = h_idx[a], vb = h_idx[b];
        h_idx[a] = vb; h_idx[b] = va;
    }
}

// ---------------------------------------------------------------------------

template <int Lc>
static void launch_band(const float* x, float* out) {
    const int smem = Lc * GW * (int)sizeof(float);
    cudaFuncSetAttribute(clop_band_t<Lc>,
                         cudaFuncAttributeMaxDynamicSharedMemorySize, smem);
    dim3 grid(NPLANES, NBANDS);
    clop_band_t<Lc><<<grid, 256, smem>>>(x, out);
}

extern "C" void kernel_launch(void* const* d_in, const int* in_sizes, int n_in,
                              void* d_out, int out_size) {
    (void)in_sizes; (void)n_in; (void)out_size;

    static int h_idx[HW];
    alignas(16) static unsigned short h_idxl[HW];   // ATS-read by copy kernel
    compute_host_idx(h_idx);

    // max toroidal row distance from each output row's band window
    int D = 0;
    for (int i = 0; i < HW; i++) {
        const int r_out = i / GW;
        const int bandstart = (r_out / BAND) * BAND;
        const int r_src = h_idx[i] / GW;
        int dist = 0;
        if (r_src >= bandstart && r_src < bandstart + BAND) {
            dist = 0;
        } else {
            int dlo = (bandstart - r_src + GH) % GH;
            int dhi = (r_src - (bandstart + BAND - 1) + GH) % GH;
            dist = dlo < dhi ? dlo : dhi;
        }
        if (dist > D) D = dist;
    }

    const float* x = (const float*)d_in[0];
    float* out = (float*)d_out;

    int Lc = 0;
    if (D <= 2)       Lc = 32;
    else if (D <= 6)  Lc = 40;
    else if (D <= 10) Lc = 48;
    else if (D <= 18) Lc = 64;

    int ats = 0;
    cudaDeviceGetAttribute(&ats, cudaDevAttrPageableMemoryAccess, 0);

    if (Lc != 0) {
        // window-relative COMPONENT-PLANE indices for padded window
        const int Dp = (Lc - BAND) / 2;
        const int S = Lc * W4;                       // plane stride in floats
        for (int i = 0; i < HW; i++) {
            const int r_out = i / GW;
            const int ws0 = (r_out / BAND) * BAND - Dp;
            const int r_src = h_idx[i] / GW;
            const int c_src = h_idx[i] % GW;
            int t = r_src - ws0;
            t %= GH; if (t < 0) t += GH;
            const int comp = c_src & 3;
            const int m    = t * W4 + (c_src >> 2);
            h_idxl[i] = (unsigned short)(comp * S + m);
        }

        if (ats) {
            write_idx_ats<<<(HW16 + 255) / 256, 256>>>(
                reinterpret_cast<const uint4*>(h_idxl));
        } else {
            cudaMemcpyToSymbolAsync(g_idxl, h_idxl, sizeof(h_idxl), 0,
                                    cudaMemcpyHostToDevice, 0);
        }

        if (Lc == 32)      launch_band<32>(x, out);
        else if (Lc == 40) launch_band<40>(x, out);
        else if (Lc == 48) launch_band<48>(x, out);
        else               launch_band<64>(x, out);
    } else {
        cudaFuncSetAttribute(clop_gather,
                             cudaFuncAttributeMaxDynamicSharedMemorySize,
                             HW * (int)sizeof(float));
        cudaMemcpyToSymbolAsync(g_idx, h_idx, sizeof(h_idx), 0,
                                cudaMemcpyHostToDevice, 0);
        clop_gather<<<NPLANES, 1024, HW * sizeof(float)>>>(x, out);
    }
}

// round 7
// speedup vs baseline: 1.2490x; 1.2490x over previous
#include <cuda_runtime.h>
#include <cstdint>
#include <cstring>
#include <vector>
#include <algorithm>

// ---------------------------------------------------------------------------
// CLOPLayer: out[b,c,i] = x[b,c,idx[i]], idx fixed (JAX threefry seed 42 +
// sequential neighbor-swap scan), recomputed bit-exact on the HOST each call;
// delivered by one ATS copy kernel (GB300 NVLink-C2C, pageableMemoryAccess=1).
//
// Gather kernel (R7): one block per (plane, band), BAND=56 output rows.
// The L-row input window is a CONTIGUOUS plane byte-range -> filled by 1-2
// cp.async.bulk (UBLKCP) DMA copies issued by one thread (zero register
// pressure, no per-warp load stalls). Warps prefetch their uint16 idx under
// the DMA, mbarrier-wait, then LDS-gather + STG.128. R6 showed smem bank
// conflicts are NOT binding, so plain row-major smem is used.
// ---------------------------------------------------------------------------

#define GH 224
#define GW 224
#define HW (GH * GW)          // 50176
#define HW4 (HW / 4)
#define NPLANES 384           // 128 * 3
#define BAND 56
#define NBANDS (GH / BAND)    // 4
#define BANDW (BAND * GW)     // 12544
#define BANDW4 (BANDW / 4)    // 3136
#define NT 512                // threads per gather block
#define GITER ((BANDW4 + NT - 1) / NT)   // 7 (last partial)
#define HW16 (HW / 8)         // uint4 units of the uint16 idx table

__device__ unsigned short g_idxl[HW];  // window-relative indices
__device__ int g_idx[HW];              // absolute indices (fallback path)

static __device__ __forceinline__ uint32_t smem_u32(const void* p) {
    uint32_t a;
    asm("{ .reg .u64 t; cvta.to.shared.u64 t, %1; cvt.u32.u64 %0, t; }"
        : "=r"(a) : "l"(p));
    return a;
}

static __device__ __forceinline__ void mbar_init(uint32_t mb, uint32_t cnt) {
    asm volatile("mbarrier.init.shared.b64 [%0], %1;" :: "r"(mb), "r"(cnt)
                 : "memory");
}
static __device__ __forceinline__ void mbar_expect_tx(uint32_t mb, uint32_t tx) {
    asm volatile("mbarrier.arrive.expect_tx.shared.b64 _, [%0], %1;"
                 :: "r"(mb), "r"(tx) : "memory");
}
static __device__ __forceinline__ void bulk_g2s(uint32_t dst, const void* src,
                                                uint32_t bytes, uint32_t mb) {
    asm volatile(
        "cp.async.bulk.shared::cluster.global.mbarrier::complete_tx::bytes "
        "[%0], [%1], %2, [%3];"
        :: "r"(dst), "l"(src), "r"(bytes), "r"(mb) : "memory");
}
static __device__ __forceinline__ void mbar_wait(uint32_t mb, uint32_t phase) {
    asm volatile(
        "{\n\t"
        ".reg .pred P;\n\t"
        "WAIT_%=: \n\t"
        "mbarrier.try_wait.parity.acquire.cta.shared::cta.b64 P, [%0], %1, 0x989680;\n\t"
        "@P bra.uni DONE_%=;\n\t"
        "bra.uni WAIT_%=;\n\t"
        "DONE_%=: \n\t"
        "}"
        :: "r"(mb), "r"(phase) : "memory");
}

// ---- host(ATS) -> device idx copy kernel ----------------------------------
__global__ __launch_bounds__(256)
void write_idx_ats(const uint4* __restrict__ hsrc) {
    int i = blockIdx.x * blockDim.x + threadIdx.x;
    if (i < HW16) {
        reinterpret_cast<uint4*>(g_idxl)[i] = __ldg(&hsrc[i]);
    }
}

// ---- banded gather with DMA fill, compile-time window height Lc ------------
template <int Lc>
__global__ __launch_bounds__(NT)
void clop_band_t(const float* __restrict__ x, float* __restrict__ out) {
    extern __shared__ float sp[];                 // Lc*GW floats, row-major
    __shared__ __align__(8) unsigned long long mbar_s;

    const int plane = blockIdx.x;
    const int band  = blockIdx.y;
    const float* src = x + (size_t)plane * HW;

    int ws = band * BAND - ((Lc - BAND) >> 1);    // toroidal window start row
    if (ws < 0) ws += GH;

    const uint32_t mb = smem_u32(&mbar_s);
    if (threadIdx.x == 0) mbar_init(mb, 1);
    __syncthreads();

    if (threadIdx.x == 0) {
        constexpr uint32_t TOTAL = (uint32_t)Lc * GW * sizeof(float);
        mbar_expect_tx(mb, TOTAL);
        const int n1 = (GH - ws < Lc) ? (GH - ws) : Lc;   // rows before wrap
        const uint32_t b1 = (uint32_t)n1 * GW * sizeof(float);
        bulk_g2s(smem_u32(sp), src + (size_t)ws * GW, b1, mb);
        if (n1 < Lc) {
            bulk_g2s(smem_u32(sp) + b1, src, TOTAL - b1, mb);
        }
    }

    // prefetch idx for this band into registers while the DMA streams
    const size_t base = (size_t)band * BANDW;
    const ushort4* id4 = reinterpret_cast<const ushort4*>(g_idxl + base);
    ushort4 idbuf[GITER];
#pragma unroll
    for (int u = 0; u < GITER; u++) {
        const int k = threadIdx.x + u * NT;
        if (k < BANDW4) idbuf[u] = __ldg(&id4[k]);
    }

    mbar_wait(mb, 0);

    float4* dst = reinterpret_cast<float4*>(out + (size_t)plane * HW + base);
#pragma unroll
    for (int u = 0; u < GITER; u++) {
        const int k = threadIdx.x + u * NT;
        if (k < BANDW4) {
            const ushort4 id = idbuf[u];
            float4 v;
            v.x = sp[id.x];
            v.y = sp[id.y];
            v.z = sp[id.z];
            v.w = sp[id.w];
            __stcs(&dst[k], v);
        }
    }
}

// ---- fallback: full-plane smem gather (proven, R1) --------------------------
__global__ __launch_bounds__(1024, 1)
void clop_gather(const float* __restrict__ x, float* __restrict__ out) {
    extern __shared__ float sp[];
    const size_t off = (size_t)blockIdx.x * HW;
    const float4* src = reinterpret_cast<const float4*>(x + off);
    float4* sp4 = reinterpret_cast<float4*>(sp);
    for (int k = threadIdx.x; k < HW4; k += 1024) sp4[k] = src[k];
    __syncthreads();
    float4* dst = reinterpret_cast<float4*>(out + off);
    const int4* idx4 = reinterpret_cast<const int4*>(g_idx);
    for (int k = threadIdx.x; k < HW4; k += 1024) {
        int4 id = __ldg(&idx4[k]);
        float4 v;
        v.x = sp[id.x]; v.y = sp[id.y]; v.z = sp[id.z]; v.w = sp[id.w];
        __stcs(&dst[k], v);
    }
}

// ---------------------------------------------------------------------------
// Host-side exact replication of the JAX RNG pipeline (partitionable threefry)
// ---------------------------------------------------------------------------

static inline uint32_t rotl32(uint32_t x, int d) {
    return (x << d) | (x >> (32 - d));
}

struct TFKey { uint32_t hi, lo; };

static void threefry2x32(uint32_t k0, uint32_t k1, uint32_t x0, uint32_t x1,
                         uint32_t* o0, uint32_t* o1) {
    const uint32_t ks0 = k0, ks1 = k1, ks2 = k0 ^ k1 ^ 0x1BD11BDAu;
    static const int ra[4] = {13, 15, 26, 6};
    static const int rb[4] = {17, 29, 16, 24};
    x0 += ks0; x1 += ks1;
    for (int i = 0; i < 4; i++) { x0 += x1; x1 = rotl32(x1, ra[i]); x1 ^= x0; }
    x0 += ks1; x1 += ks2 + 1u;
    for (int i = 0; i < 4; i++) { x0 += x1; x1 = rotl32(x1, rb[i]); x1 ^= x0; }
    x0 += ks2; x1 += ks0 + 2u;
    for (int i = 0; i < 4; i++) { x0 += x1; x1 = rotl32(x1, ra[i]); x1 ^= x0; }
    x0 += ks0; x1 += ks1 + 3u;
    for (int i = 0; i < 4; i++) { x0 += x1; x1 = rotl32(x1, rb[i]); x1 ^= x0; }
    x0 += ks1; x1 += ks2 + 4u;
    for (int i = 0; i < 4; i++) { x0 += x1; x1 = rotl32(x1, ra[i]); x1 ^= x0; }
    x0 += ks2; x1 += ks0 + 5u;
    *o0 = x0; *o1 = x1;
}

static inline TFKey tf_child(TFKey k, uint32_t j) {
    TFKey r; threefry2x32(k.hi, k.lo, 0u, j, &r.hi, &r.lo); return r;
}
static inline uint32_t tf_bits32(TFKey k, uint32_t i) {
    uint32_t a, b; threefry2x32(k.hi, k.lo, 0u, i, &a, &b); return a ^ b;
}

static void compute_host_idx(int* h_idx) {
    const int n = HW;
    TFKey key42 = {0u, 42u};
    TFKey k1 = tf_child(key42, 0u);
    TFKey k2 = tf_child(key42, 1u);

    std::vector<int> order(n);
    for (int i = 0; i < n; i++) order[i] = i;
    {
        TFKey cur = k1;
        std::vector<uint64_t> kv(n);
        std::vector<int> nx(n);
        for (int round = 0; round < 2; round++) {
            TFKey nkey = tf_child(cur, 0u);
            TFKey sub  = tf_child(cur, 1u);
            for (int i = 0; i < n; i++)
                kv[(size_t)i] = ((uint64_t)tf_bits32(sub, (uint32_t)i) << 32) |
                                (uint32_t)i;
            std::sort(kv.begin(), kv.end());
            for (int j = 0; j < n; j++)
                nx[(size_t)j] = order[(size_t)(uint32_t)kv[(size_t)j]];
            order.swap(nx);
            cur = nkey;
        }
    }

    float p0 = (float)(1.0 - 0.3), pq = (float)(0.3 / 4.0);
    float c[5];
    c[0] = p0;
    for (int j = 1; j < 5; j++) c[j] = c[j - 1] + pq;

    std::vector<uint8_t> rs(n);
    for (int i = 0; i < n; i++) {
        uint32_t bits = tf_bits32(k2, (uint32_t)i);
        uint32_t fb = (bits >> 9) | 0x3F800000u;
        float f; std::memcpy(&f, &fb, 4);
        f -= 1.0f;
        float r = c[4] * (1.0f - f);
        int ind = 0;
        while (ind < 5 && c[ind] < r) ind++;
        rs[(size_t)i] = (uint8_t)ind;
    }

    for (int i = 0; i < n; i++) h_idx[i] = i;
    for (int t = 0; t < n; t++) {
        const int a = order[(size_t)t];
        const int r = rs[(size_t)t];
        const int i = a / GW, j = a % GW;
        const int ii = (r == 1) ? (i + 1) % GH : (r == 2) ? (i + GH - 1) % GH : i;
        const int jj = (r == 3) ? (j + 1) % GW : (r == 4) ? (j + GW - 1) % GW : j;
        const int b = (r == 0) ? a : (ii * GW + jj);
        const int va = h_idx[a], vb = h_idx[b];
        h_idx[a] = vb; h_idx[b] = va;
    }
}

// ---------------------------------------------------------------------------

template <int Lc>
static void launch_band(const float* x, float* out) {
    const int smem = Lc * GW * (int)sizeof(float);
    cudaFuncSetAttribute(clop_band_t<Lc>,
                         cudaFuncAttributeMaxDynamicSharedMemorySize, smem);
    dim3 grid(NPLANES, NBANDS);
    clop_band_t<Lc><<<grid, NT, smem>>>(x, out);
}

extern "C" void kernel_launch(void* const* d_in, const int* in_sizes, int n_in,
                              void* d_out, int out_size) {
    (void)in_sizes; (void)n_in; (void)out_size;

    static int h_idx[HW];
    alignas(16) static unsigned short h_idxl[HW];   // ATS-read by copy kernel
    compute_host_idx(h_idx);

    // max toroidal row distance from each output row's band window
    int D = 0;
    for (int i = 0; i < HW; i++) {
        const int r_out = i / GW;
        const int bandstart = (r_out / BAND) * BAND;
        const int r_src = h_idx[i] / GW;
        int dist = 0;
        if (r_src >= bandstart && r_src < bandstart + BAND) {
            dist = 0;
        } else {
            int dlo = (bandstart - r_src + GH) % GH;
            int dhi = (r_src - (bandstart + BAND - 1) + GH) % GH;
            dist = dlo < dhi ? dlo : dhi;
        }
        if (dist > D) D = dist;
    }

    const float* x = (const float*)d_in[0];
    float* out = (float*)d_out;

    // compile-time window heights: L = BAND + 2*Dp, padded up
    int Lc = 0;
    if (D <= 2)       Lc = 60;
    else if (D <= 6)  Lc = 68;
    else if (D <= 10) Lc = 76;
    else if (D <= 18) Lc = 92;

    int ats = 0;
    cudaDeviceGetAttribute(&ats, cudaDevAttrPageableMemoryAccess, 0);

    if (Lc != 0) {
        // window-relative row-major indices for the padded window
        const int Dp = (Lc - BAND) / 2;
        for (int i = 0; i < HW; i++) {
            const int r_out = i / GW;
            const int ws0 = (r_out / BAND) * BAND - Dp;
            const int r_src = h_idx[i] / GW;
            const int c_src = h_idx[i] % GW;
            int t = r_src - ws0;
            t %= GH; if (t < 0) t += GH;
            h_idxl[i] = (unsigned short)(t * GW + c_src);
        }

        if (ats) {
            write_idx_ats<<<(HW16 + 255) / 256, 256>>>(
                reinterpret_cast<const uint4*>(h_idxl));
        } else {
            cudaMemcpyToSymbolAsync(g_idxl, h_idxl, sizeof(h_idxl), 0,
                                    cudaMemcpyHostToDevice, 0);
        }

        if (Lc == 60)      launch_band<60>(x, out);
        else if (Lc == 68) launch_band<68>(x, out);
        else if (Lc == 76) launch_band<76>(x, out);
        else               launch_band<92>(x, out);
    } else {
        cudaFuncSetAttribute(clop_gather,
                             cudaFuncAttributeMaxDynamicSharedMemorySize,
                             HW * (int)sizeof(float));
        cudaMemcpyToSymbolAsync(g_idx, h_idx, sizeof(h_idx), 0,
                                cudaMemcpyHostToDevice, 0);
        clop_gather<<<NPLANES, 1024, HW * sizeof(float)>>>(x, out);
    }
}